// round 9
// baseline (speedup 1.0000x reference)
#include <cuda_runtime.h>

// Problem constants
#define HW    115200      // 240*480
#define HW4   28800       // HW/4
#define C_    128
#define L_    4
#define R_    8
#define KK    36
#define CH    64
#define WF    (C_*R_ + R_*KK)   // 1312

// Scratch (allocation-free: __device__ globals)
__device__ float g_ctx[L_*C_];

// -------------------------------------------------------------------------
// K1: ctx[l,c] = mean over HW of x[l,c,:,:].  512 blocks x 256 threads.
// Reads lc ascending -> x[l=2,3] is L2-resident when this finishes.
// (Proven ~39us @ 77.5% DRAM.)
// -------------------------------------------------------------------------
__global__ void __launch_bounds__(256)
mean_kernel(const float* __restrict__ x) {
    const int lc = blockIdx.x;
    const float4* xp = reinterpret_cast<const float4*>(x + (size_t)lc * HW);
    float s = 0.f;
    for (int i = threadIdx.x; i < HW4; i += 256) {
        float4 v = xp[i];
        s += (v.x + v.y) + (v.z + v.w);
    }
    __shared__ float red[8];
    #pragma unroll
    for (int o = 16; o; o >>= 1) s += __shfl_down_sync(0xffffffffu, s, o);
    if ((threadIdx.x & 31) == 0) red[threadIdx.x >> 5] = s;
    __syncthreads();
    if (threadIdx.x < 8) {
        s = red[threadIdx.x];
        #pragma unroll
        for (int o = 4; o; o >>= 1) s += __shfl_down_sync(0xffu, s, o);
        if (threadIdx.x == 0) g_ctx[lc] = s * (1.0f / (float)HW);
    }
}

// -------------------------------------------------------------------------
// K2: out = x + (gain*W1) @ (W2 @ Y), with the hypernet fused into the
// block prologue (redundant per block; ~360 FMA/thread, Wb is L2-resident).
// grid (113, 2); l = l_base + blockIdx.y. Launched twice: l_base=2 first
// (x[l=2,3] still L2-resident from mean), then l_base=0.
// x loads use .cs (read-once), out stores .cs (evict-first): keeps L2 for
// Y and the residual x.
// -------------------------------------------------------------------------
__global__ void __launch_bounds__(256, 3)
apply_kernel(const float* __restrict__ x,
             const float* __restrict__ Y,
             const float* __restrict__ Wa, const float* __restrict__ ba,
             const float* __restrict__ Wb, const float* __restrict__ bb,
             const float* __restrict__ gain,
             float* __restrict__ out, int l_base) {
    const int l = l_base + blockIdx.y;
    const int tid = threadIdx.x;

    __shared__ float ctx_s[C_];
    __shared__ float h_s[CH];
    __shared__ float w1s[C_*R_];
    __shared__ float w2s[R_*KK];

    // --- fused hypernet (this block's l only) ---
    if (tid < C_) ctx_s[tid] = g_ctx[l*C_ + tid];
    __syncthreads();
    if (tid < CH) {
        float acc = ba[tid];
        #pragma unroll 8
        for (int c = 0; c < C_; c++) acc += ctx_s[c] * Wa[c*CH + tid];
        float sg = 1.f / (1.f + expf(-acc));
        h_s[tid] = acc * sg;
    }
    __syncthreads();
    for (int o = tid; o < WF; o += 256) {
        float acc = bb[o];
        #pragma unroll 8
        for (int j = 0; j < CH; j++) acc += h_s[j] * Wb[j*WF + o];
        if (o < C_*R_) w1s[o] = acc * gain[o >> 3];
        else           w2s[o - C_*R_] = acc;
    }
    __syncthreads();

    const int p4 = blockIdx.x * 256 + tid;
    if (p4 >= HW4) return;

    // --- z[r] = sum_k W2[r,k] * Y[k,p]  (Y L2-resident after first wave) ---
    const float4* Y4 = reinterpret_cast<const float4*>(Y);
    float4 z[R_];
    #pragma unroll
    for (int r = 0; r < R_; r++) z[r] = make_float4(0.f, 0.f, 0.f, 0.f);

    for (int kc = 0; kc < KK; kc += 6) {          // 6 chunks x 6 loads (MLP=6)
        float4 y[6];
        #pragma unroll
        for (int j = 0; j < 6; j++)
            y[j] = Y4[(size_t)(kc + j) * HW4 + p4];
        #pragma unroll
        for (int j = 0; j < 6; j++) {
            #pragma unroll
            for (int r = 0; r < R_; r++) {
                float w = w2s[r*KK + kc + j];
                z[r].x = fmaf(w, y[j].x, z[r].x);
                z[r].y = fmaf(w, y[j].y, z[r].y);
                z[r].z = fmaf(w, y[j].z, z[r].z);
                z[r].w = fmaf(w, y[j].w, z[r].w);
            }
        }
    }

    // --- c-loop: 8 front-batched streaming loads (MLP=8) ---
    const float4* x4 = reinterpret_cast<const float4*>(x);
    float4*       o4 = reinterpret_cast<float4*>(out);
    const size_t base = (size_t)l * C_ * HW4 + p4;

    for (int cc = 0; cc < C_; cc += 8) {
        float4 xv[8];
        #pragma unroll
        for (int j = 0; j < 8; j++)
            xv[j] = __ldcs(&x4[base + (size_t)(cc + j) * HW4]);
        #pragma unroll
        for (int j = 0; j < 8; j++) {
            float4 acc = make_float4(0.f, 0.f, 0.f, 0.f);
            const int c = cc + j;
            #pragma unroll
            for (int r = 0; r < R_; r++) {
                float w = w1s[c*R_ + r];
                acc.x = fmaf(w, z[r].x, acc.x);
                acc.y = fmaf(w, z[r].y, acc.y);
                acc.z = fmaf(w, z[r].z, acc.z);
                acc.w = fmaf(w, z[r].w, acc.w);
            }
            xv[j].x += acc.x;
            xv[j].y += acc.y;
            xv[j].z += acc.z;
            xv[j].w += acc.w;
            __stcs(&o4[base + (size_t)c * HW4], xv[j]);
        }
    }
}

// -------------------------------------------------------------------------
// launch.  Inputs (metadata order): x, Wa, ba, Wb, bb, gain, Y  (all f32)
// -------------------------------------------------------------------------
extern "C" void kernel_launch(void* const* d_in, const int* in_sizes, int n_in,
                              void* d_out, int out_size) {
    const float* x    = (const float*)d_in[0];
    const float* Wa   = (const float*)d_in[1];
    const float* ba   = (const float*)d_in[2];
    const float* Wb   = (const float*)d_in[3];
    const float* bb   = (const float*)d_in[4];
    const float* gain = (const float*)d_in[5];
    const float* Y    = (const float*)d_in[6];
    float* out = (float*)d_out;

    dim3 grid((HW4 + 255)/256, 2);
    mean_kernel<<<L_*C_, 256>>>(x);
    // l=2,3 first: their x slices are still L2-resident from mean's tail
    apply_kernel<<<grid, 256>>>(x, Y, Wa, ba, Wb, bb, gain, out, 2);
    apply_kernel<<<grid, 256>>>(x, Y, Wa, ba, Wb, bb, gain, out, 0);
}

// round 13
// speedup vs baseline: 1.2522x; 1.2522x over previous
#include <cuda_runtime.h>

// Problem constants
#define HW    115200      // 240*480
#define HW4   28800       // HW/4
#define C_    128
#define L_    4
#define R_    8
#define KK    36
#define CH    64
#define WF    (C_*R_ + R_*KK)   // 1312

// Scratch (allocation-free: __device__ globals)
__device__ float g_ctx[L_*C_];
__device__ float g_W1[L_*C_*R_];          // pre-scaled by gain[c]
__device__ float g_W2[L_*R_*KK];
__device__ float g_Z[L_*R_*HW];           // Z[l,r,p] (14.7 MB, L2-resident)

// -------------------------------------------------------------------------
// K1: ctx[l,c] = mean over HW of x[l,c,:,:].  512 blocks x 256 threads.
// (Proven ~39us @ 77% DRAM — at achieved roofline.)
// -------------------------------------------------------------------------
__global__ void __launch_bounds__(256)
mean_kernel(const float* __restrict__ x) {
    const int lc = blockIdx.x;
    const float4* xp = reinterpret_cast<const float4*>(x + (size_t)lc * HW);
    float s = 0.f;
    for (int i = threadIdx.x; i < HW4; i += 256) {
        float4 v = xp[i];
        s += (v.x + v.y) + (v.z + v.w);
    }
    __shared__ float red[8];
    #pragma unroll
    for (int o = 16; o; o >>= 1) s += __shfl_down_sync(0xffffffffu, s, o);
    if ((threadIdx.x & 31) == 0) red[threadIdx.x >> 5] = s;
    __syncthreads();
    if (threadIdx.x < 8) {
        s = red[threadIdx.x];
        #pragma unroll
        for (int o = 4; o; o >>= 1) s += __shfl_down_sync(0xffu, s, o);
        if (threadIdx.x == 0) g_ctx[lc] = s * (1.0f / (float)HW);
    }
}

// -------------------------------------------------------------------------
// K2: full hypernet. 21 blocks x 256 threads (proven ~2us).
// -------------------------------------------------------------------------
__global__ void __launch_bounds__(256)
hyper_kernel(const float* __restrict__ Wa, const float* __restrict__ ba,
             const float* __restrict__ Wb, const float* __restrict__ bb,
             const float* __restrict__ gain) {
    __shared__ float ctx_s[L_*C_];
    __shared__ float h_s[L_*CH];
    const int tid = threadIdx.x;

    for (int i = tid; i < L_*C_; i += 256) ctx_s[i] = g_ctx[i];
    __syncthreads();

    {   // h: 256 threads == 4*64 outputs
        const int l = tid / CH, j = tid % CH;
        float acc = ba[j];
        #pragma unroll 8
        for (int c = 0; c < C_; c++) acc += ctx_s[l*C_ + c] * Wa[c*CH + j];
        float sg = 1.f / (1.f + expf(-acc));
        h_s[l*CH + j] = acc * sg;
    }
    __syncthreads();

    const int idx = blockIdx.x * 256 + tid;
    if (idx >= L_*WF) return;
    const int l = idx / WF, o = idx % WF;
    float acc = bb[o];
    #pragma unroll 8
    for (int j = 0; j < CH; j++) acc += h_s[l*CH + j] * Wb[j*WF + o];
    if (o < C_*R_) g_W1[l*C_*R_ + o] = acc * gain[o / R_];
    else           g_W2[l*R_*KK + (o - C_*R_)] = acc;
}

// -------------------------------------------------------------------------
// K3: Z[l,r,p] = sum_k W2[l,r,k] * Y[k,p].
// REWORKED vs R4 (was 17.9us, 928GB/s, 128-thr blocks, spill-prone):
// 256-thr blocks, grid (113, 4); 6x6 chunked Y loads (MLP=6); ~56 live regs.
// Z stays in L2 (14.7MB) for apply to read.
// -------------------------------------------------------------------------
__global__ void __launch_bounds__(256, 3)
zcomp_kernel(const float* __restrict__ Y) {
    const int l = blockIdx.y;

    __shared__ float w2s[R_*KK];
    for (int i = threadIdx.x; i < R_*KK; i += 256) w2s[i] = g_W2[l*R_*KK + i];
    __syncthreads();

    const int p4 = blockIdx.x * 256 + threadIdx.x;
    if (p4 >= HW4) return;

    const float4* Y4 = reinterpret_cast<const float4*>(Y);
    float4 z[R_];
    #pragma unroll
    for (int r = 0; r < R_; r++) z[r] = make_float4(0.f, 0.f, 0.f, 0.f);

    for (int kc = 0; kc < KK; kc += 6) {          // 6 chunks x 6 loads
        float4 y[6];
        #pragma unroll
        for (int j = 0; j < 6; j++)
            y[j] = Y4[(size_t)(kc + j) * HW4 + p4];
        #pragma unroll
        for (int j = 0; j < 6; j++) {
            #pragma unroll
            for (int r = 0; r < R_; r++) {
                float w = w2s[r*KK + kc + j];
                z[r].x = fmaf(w, y[j].x, z[r].x);
                z[r].y = fmaf(w, y[j].y, z[r].y);
                z[r].z = fmaf(w, y[j].z, z[r].z);
                z[r].w = fmaf(w, y[j].w, z[r].w);
            }
        }
    }

    float4* Z4 = reinterpret_cast<float4*>(g_Z);
    #pragma unroll
    for (int r = 0; r < R_; r++)
        Z4[(size_t)(l*R_ + r) * HW4 + p4] = z[r];
}

// -------------------------------------------------------------------------
// K4: out = x + (gain*W1) @ Z.  VERBATIM the R4/R5 kernel measured at
// 75.5us / 6.0TB/s (904 blocks, 64 regs, batch-8 c-loop, MLP=8).
// -------------------------------------------------------------------------
__global__ void __launch_bounds__(256)
apply_kernel(const float* __restrict__ x,
             float* __restrict__ out) {
    const int l  = blockIdx.y;
    const int c0 = blockIdx.z * (C_/2);   // 0 or 64

    __shared__ float w1s[(C_/2)*R_];
    for (int i = threadIdx.x; i < (C_/2)*R_; i += 256)
        w1s[i] = g_W1[l*C_*R_ + c0*R_ + i];
    __syncthreads();

    const int p4 = blockIdx.x * 256 + threadIdx.x;
    if (p4 >= HW4) return;

    const float4* Z4 = reinterpret_cast<const float4*>(g_Z);
    float4 z[R_];
    #pragma unroll
    for (int r = 0; r < R_; r++)
        z[r] = Z4[(size_t)(l*R_ + r) * HW4 + p4];

    const float4* x4 = reinterpret_cast<const float4*>(x);
    float4*       o4 = reinterpret_cast<float4*>(out);
    const size_t base = ((size_t)l * C_ + c0) * HW4 + p4;

    for (int cc = 0; cc < C_/2; cc += 8) {
        float4 xv[8];
        #pragma unroll
        for (int j = 0; j < 8; j++)
            xv[j] = x4[base + (size_t)(cc + j) * HW4];
        #pragma unroll
        for (int j = 0; j < 8; j++) {
            float4 acc = make_float4(0.f, 0.f, 0.f, 0.f);
            const int c = cc + j;
            #pragma unroll
            for (int r = 0; r < R_; r++) {
                float w = w1s[c*R_ + r];
                acc.x = fmaf(w, z[r].x, acc.x);
                acc.y = fmaf(w, z[r].y, acc.y);
                acc.z = fmaf(w, z[r].z, acc.z);
                acc.w = fmaf(w, z[r].w, acc.w);
            }
            xv[j].x += acc.x;
            xv[j].y += acc.y;
            xv[j].z += acc.z;
            xv[j].w += acc.w;
            o4[base + (size_t)c * HW4] = xv[j];
        }
    }
}

// -------------------------------------------------------------------------
// launch.  Inputs (metadata order): x, Wa, ba, Wb, bb, gain, Y  (all f32)
// -------------------------------------------------------------------------
extern "C" void kernel_launch(void* const* d_in, const int* in_sizes, int n_in,
                              void* d_out, int out_size) {
    const float* x    = (const float*)d_in[0];
    const float* Wa   = (const float*)d_in[1];
    const float* ba   = (const float*)d_in[2];
    const float* Wb   = (const float*)d_in[3];
    const float* bb   = (const float*)d_in[4];
    const float* gain = (const float*)d_in[5];
    const float* Y    = (const float*)d_in[6];
    float* out = (float*)d_out;

    mean_kernel<<<L_*C_, 256>>>(x);
    hyper_kernel<<<(L_*WF + 255)/256, 256>>>(Wa, ba, Wb, bb, gain);
    zcomp_kernel<<<dim3((HW4 + 255)/256, L_), 256>>>(Y);
    apply_kernel<<<dim3((HW4 + 255)/256, L_, 2), 256>>>(x, out);
}

// round 14
// speedup vs baseline: 1.2673x; 1.0121x over previous
#include <cuda_runtime.h>

// Problem constants
#define HW    115200      // 240*480
#define HW4   28800       // HW/4
#define C_    128
#define L_    4
#define R_    8
#define KK    36
#define CH    64
#define WF    (C_*R_ + R_*KK)   // 1312

// Scratch (allocation-free: __device__ globals)
__device__ float g_ctx[L_*C_];
__device__ float g_W1[L_*C_*R_];          // pre-scaled by gain[c]
__device__ float g_W2[L_*R_*KK];

// -------------------------------------------------------------------------
// K1: ctx[l,c] = mean over HW of x[l,c,:,:].  512 blocks x 256 threads.
// (Proven ~39us @ 77% DRAM — at achieved roofline. FROZEN.)
// -------------------------------------------------------------------------
__global__ void __launch_bounds__(256)
mean_kernel(const float* __restrict__ x) {
    const int lc = blockIdx.x;
    const float4* xp = reinterpret_cast<const float4*>(x + (size_t)lc * HW);
    float s = 0.f;
    for (int i = threadIdx.x; i < HW4; i += 256) {
        float4 v = xp[i];
        s += (v.x + v.y) + (v.z + v.w);
    }
    __shared__ float red[8];
    #pragma unroll
    for (int o = 16; o; o >>= 1) s += __shfl_down_sync(0xffffffffu, s, o);
    if ((threadIdx.x & 31) == 0) red[threadIdx.x >> 5] = s;
    __syncthreads();
    if (threadIdx.x < 8) {
        s = red[threadIdx.x];
        #pragma unroll
        for (int o = 4; o; o >>= 1) s += __shfl_down_sync(0xffu, s, o);
        if (threadIdx.x == 0) g_ctx[lc] = s * (1.0f / (float)HW);
    }
}

// -------------------------------------------------------------------------
// K2: full hypernet. 21 blocks x 256 threads (proven ~2us).
// -------------------------------------------------------------------------
__global__ void __launch_bounds__(256)
hyper_kernel(const float* __restrict__ Wa, const float* __restrict__ ba,
             const float* __restrict__ Wb, const float* __restrict__ bb,
             const float* __restrict__ gain) {
    __shared__ float ctx_s[L_*C_];
    __shared__ float h_s[L_*CH];
    const int tid = threadIdx.x;

    for (int i = tid; i < L_*C_; i += 256) ctx_s[i] = g_ctx[i];
    __syncthreads();

    {   // h: 256 threads == 4*64 outputs
        const int l = tid / CH, j = tid % CH;
        float acc = ba[j];
        #pragma unroll 8
        for (int c = 0; c < C_; c++) acc += ctx_s[l*C_ + c] * Wa[c*CH + j];
        float sg = 1.f / (1.f + expf(-acc));
        h_s[l*CH + j] = acc * sg;
    }
    __syncthreads();

    const int idx = blockIdx.x * 256 + tid;
    if (idx >= L_*WF) return;
    const int l = idx / WF, o = idx % WF;
    float acc = bb[o];
    #pragma unroll 8
    for (int j = 0; j < CH; j++) acc += h_s[l*CH + j] * Wb[j*WF + o];
    if (o < C_*R_) g_W1[l*C_*R_ + o] = acc * gain[o / R_];
    else           g_W2[l*R_*KK + (o - C_*R_)] = acc;
}

// -------------------------------------------------------------------------
// K3: out = x + (gain*W1) @ (W2 @ Y), fused, SINGLE WAVE.
// grid (113, 4) = 452 blocks, occ-4 (592 slots) -> no straggler wave.
// z computed in regs (9x4 chunks), parked in smem (thread-private slots),
// c-loop: xv[8] batch (MLP=8), r-outer with one z_r in regs (~50 live regs).
// -------------------------------------------------------------------------
__global__ void __launch_bounds__(256, 4)
apply_kernel(const float* __restrict__ x,
             const float* __restrict__ Y,
             float* __restrict__ out) {
    const int l = blockIdx.y;
    const int tid = threadIdx.x;

    __shared__ float  w1s[C_*R_];         // 4 KB
    __shared__ float  w2s[R_*KK];         // 1.2 KB
    __shared__ float4 zs[R_*256];         // 32 KB (thread-private slots)

    for (int i = tid; i < C_*R_; i += 256) w1s[i] = g_W1[l*C_*R_ + i];
    for (int i = tid; i < R_*KK; i += 256) w2s[i] = g_W2[l*R_*KK + i];
    __syncthreads();

    const int p4 = blockIdx.x * 256 + tid;
    if (p4 >= HW4) return;

    // --- prologue: z[r] = sum_k w2s[r,k] * Y[k,p] ---
    {
        const float4* Y4 = reinterpret_cast<const float4*>(Y);
        float4 z[R_];
        #pragma unroll
        for (int r = 0; r < R_; r++) z[r] = make_float4(0.f, 0.f, 0.f, 0.f);

        for (int kc = 0; kc < KK; kc += 4) {      // 9 chunks x 4 loads
            float4 y[4];
            #pragma unroll
            for (int j = 0; j < 4; j++)
                y[j] = Y4[(size_t)(kc + j) * HW4 + p4];
            #pragma unroll
            for (int j = 0; j < 4; j++) {
                #pragma unroll
                for (int r = 0; r < R_; r++) {
                    float w = w2s[r*KK + kc + j];
                    z[r].x = fmaf(w, y[j].x, z[r].x);
                    z[r].y = fmaf(w, y[j].y, z[r].y);
                    z[r].z = fmaf(w, y[j].z, z[r].z);
                    z[r].w = fmaf(w, y[j].w, z[r].w);
                }
            }
        }
        #pragma unroll
        for (int r = 0; r < R_; r++) zs[r*256 + tid] = z[r];  // own slot, no sync
    }

    // --- c-loop: 8 front-batched x loads, r-outer accumulate into xv ---
    const float4* x4 = reinterpret_cast<const float4*>(x);
    float4*       o4 = reinterpret_cast<float4*>(out);
    const size_t base = (size_t)l * C_ * HW4 + p4;

    for (int cc = 0; cc < C_; cc += 8) {
        float4 xv[8];
        #pragma unroll
        for (int j = 0; j < 8; j++)
            xv[j] = x4[base + (size_t)(cc + j) * HW4];
        #pragma unroll
        for (int r = 0; r < R_; r++) {
            const float4 zr = zs[r*256 + tid];
            #pragma unroll
            for (int j = 0; j < 8; j++) {
                float w = w1s[(cc + j)*R_ + r];
                xv[j].x = fmaf(w, zr.x, xv[j].x);
                xv[j].y = fmaf(w, zr.y, xv[j].y);
                xv[j].z = fmaf(w, zr.z, xv[j].z);
                xv[j].w = fmaf(w, zr.w, xv[j].w);
            }
        }
        #pragma unroll
        for (int j = 0; j < 8; j++)
            o4[base + (size_t)(cc + j) * HW4] = xv[j];
    }
}

// -------------------------------------------------------------------------
// launch.  Inputs (metadata order): x, Wa, ba, Wb, bb, gain, Y  (all f32)
// -------------------------------------------------------------------------
extern "C" void kernel_launch(void* const* d_in, const int* in_sizes, int n_in,
                              void* d_out, int out_size) {
    const float* x    = (const float*)d_in[0];
    const float* Wa   = (const float*)d_in[1];
    const float* ba   = (const float*)d_in[2];
    const float* Wb   = (const float*)d_in[3];
    const float* bb   = (const float*)d_in[4];
    const float* gain = (const float*)d_in[5];
    const float* Y    = (const float*)d_in[6];
    float* out = (float*)d_out;

    mean_kernel<<<L_*C_, 256>>>(x);
    hyper_kernel<<<(L_*WF + 255)/256, 256>>>(Wa, ba, Wb, bb, gain);
    apply_kernel<<<dim3((HW4 + 255)/256, L_), 256>>>(x, Y, out);
}